// round 8
// baseline (speedup 1.0000x reference)
#include <cuda_runtime.h>
#include <cuda_bf16.h>
#include <cstdint>

#define NN   100000
#define EE   1600000
#define NB_SCAN 391   // ceil(NN/256)

// ---------------- scratch (static device globals; no allocation) ----------------
__device__ __align__(16) float g_h[(size_t)NN * 128];     // post-GEMM activations
__device__ __align__(16) float g_agg[(size_t)NN * 128];   // aggregated layer output
__device__ int   g_deg[NN];
__device__ int   g_cur[NN];
__device__ float g_dis[NN];          // (deg+1)^{-1/2}
__device__ int   g_start[NN + 1];    // CSR row offsets
__device__ int   g_part[NB_SCAN];
__device__ int   g_col[EE];          // CSR: source node per edge
__device__ float g_norm[EE];         // CSR: edge weight
__device__ int   g_is64;             // edge_index dtype flag

// ---------------- edge dtype detection ----------------
__global__ void k_dtype(const unsigned long long* __restrict__ ei) {
    __shared__ int bad;
    if (threadIdx.x == 0) bad = 0;
    __syncthreads();
    for (int t = threadIdx.x; t < 4096; t += 256)
        if (ei[t] >> 32) bad = 1;
    __syncthreads();
    if (threadIdx.x == 0) g_is64 = bad ? 0 : 1;
}

__device__ __forceinline__ unsigned edge_val(const void* ei, int pos) {
    if (g_is64) return (unsigned)((const long long*)ei)[pos];
    return (unsigned)((const int*)ei)[pos];
}

// ---------------- graph precompute ----------------
__global__ void k_zero() {
    int i = blockIdx.x * blockDim.x + threadIdx.x;
    if (i < NN) { g_deg[i] = 0; g_cur[i] = 0; }
}

__global__ void k_count(const void* __restrict__ ei) {
    int e = blockIdx.x * blockDim.x + threadIdx.x;
    if (e < EE) {
        unsigned r = edge_val(ei, e);
        if (r < NN) atomicAdd(&g_deg[r], 1);
    }
}

__global__ void k_dis() {
    int i = blockIdx.x * blockDim.x + threadIdx.x;
    if (i < NN) g_dis[i] = rsqrtf((float)g_deg[i] + 1.0f);
}

__global__ void k_scan1() {
    __shared__ int s[256];
    int t = threadIdx.x;
    int i = blockIdx.x * 256 + t;
    int v = (i < NN) ? g_deg[i] : 0;
    s[t] = v;
    __syncthreads();
#pragma unroll
    for (int off = 1; off < 256; off <<= 1) {
        int x = (t >= off) ? s[t - off] : 0;
        __syncthreads();
        s[t] += x;
        __syncthreads();
    }
    if (i < NN) g_start[i] = s[t] - v;
    if (t == 255) g_part[blockIdx.x] = s[255];
}

__global__ void k_scan2() {
    __shared__ int s[512];
    int t = threadIdx.x;
    int v = (t < NB_SCAN) ? g_part[t] : 0;
    s[t] = v;
    __syncthreads();
#pragma unroll
    for (int off = 1; off < 512; off <<= 1) {
        int x = (t >= off) ? s[t - off] : 0;
        __syncthreads();
        s[t] += x;
        __syncthreads();
    }
    if (t < NB_SCAN) g_part[t] = s[t] - v;
}

__global__ void k_scan3() {
    int i = blockIdx.x * blockDim.x + threadIdx.x;
    if (i < NN) g_start[i] += g_part[i >> 8];
    if (i == 0) g_start[NN] = EE;
}

__global__ void k_place(const void* __restrict__ ei) {
    int e = blockIdx.x * blockDim.x + threadIdx.x;
    if (e < EE) {
        unsigned r = edge_val(ei, e);
        unsigned c = edge_val(ei, EE + e);
        if (r < NN && c < NN) {
            int pos = g_start[r] + atomicAdd(&g_cur[r], 1);
            g_col[pos]  = (int)c;
            g_norm[pos] = g_dis[r] * g_dis[c];
        }
    }
}

// ---------------- split-bf16 HMMA GEMM (mma.sync.m16n8k16) ----------------
// g_h[M, Nc] = act(A[M,128]) @ W[128, Nc]
// A = Ah + Al, W = Wh + Wl (bf16 pairs); acc += Ah*Wh + Ah*Wl + Al*Wh (fp32).
// Block: 128m x 64n, 8 warps (4m x 2n), warp tile 32m x 32n.
#define LDA 136   // padded bf16 elements per smem row (+16B -> conflict-free frags)

__device__ __forceinline__ void mma16816(float* c, const uint32_t* a, const uint32_t* b) {
    asm volatile(
        "mma.sync.aligned.m16n8k16.row.col.f32.bf16.bf16.f32 "
        "{%0,%1,%2,%3}, {%4,%5,%6,%7}, {%8,%9}, {%0,%1,%2,%3};"
        : "+f"(c[0]), "+f"(c[1]), "+f"(c[2]), "+f"(c[3])
        : "r"(a[0]), "r"(a[1]), "r"(a[2]), "r"(a[3]), "r"(b[0]), "r"(b[1]));
}

template <bool RELU, bool A_FROM_AGG>
__global__ __launch_bounds__(256) void k_hmma(const float* __restrict__ Aext,
                                              const float* __restrict__ W, int Nc)
{
    extern __shared__ char smem[];
    __nv_bfloat16* Ah = (__nv_bfloat16*)smem;          // [128][LDA]
    __nv_bfloat16* Al = Ah + 128 * LDA;
    __nv_bfloat16* Bh = Al + 128 * LDA;                // [64][LDA]  (W^T: n rows, k cols)
    __nv_bfloat16* Bl = Bh + 64 * LDA;

    const float* A = A_FROM_AGG ? (const float*)g_agg : Aext;
    const int tid  = threadIdx.x;
    const int wid  = tid >> 5;
    const int lane = tid & 31;
    const int m0   = blockIdx.x * 128;
    const int n0   = blockIdx.y * 64;
    const int mrow = (wid & 3) * 32;     // warp m offset in tile
    const int ncol = (wid >> 2) * 32;    // warp n offset in tile

    // ---- stage A: 128x128 fp32 -> bf16 hi/lo ----
    for (int idx = tid; idx < 128 * 128; idx += 256) {
        int row = idx >> 7, col = idx & 127;
        float v = 0.0f;
        if (m0 + row < NN) v = A[(size_t)(m0 + row) * 128 + col];
        if (RELU) v = fmaxf(v, 0.0f);
        __nv_bfloat16 hi = __float2bfloat16(v);
        __nv_bfloat16 lo = __float2bfloat16(v - __bfloat162float(hi));
        Ah[row * LDA + col] = hi;
        Al[row * LDA + col] = lo;
    }
    // ---- stage B: W^T [64 n][128 k], n >= Nc zero-filled ----
    for (int idx = tid; idx < 64 * 128; idx += 256) {
        int k = idx >> 6, n = idx & 63;
        float v = (n0 + n < Nc) ? W[(size_t)k * Nc + n0 + n] : 0.0f;
        __nv_bfloat16 hi = __float2bfloat16(v);
        __nv_bfloat16 lo = __float2bfloat16(v - __bfloat162float(hi));
        Bh[n * LDA + k] = hi;
        Bl[n * LDA + k] = lo;
    }
    __syncthreads();

    // ---- mainloop: 3 products x 8 K-steps into same fp32 accumulators ----
    float acc[2][4][4];
#pragma unroll
    for (int mt = 0; mt < 2; mt++)
#pragma unroll
        for (int nt = 0; nt < 4; nt++)
#pragma unroll
            for (int r = 0; r < 4; r++) acc[mt][nt][r] = 0.0f;

    const int fr = lane >> 2;          // fragment row group 0..7
    const int fc = (lane & 3) * 2;     // fragment col pair

#pragma unroll
    for (int p = 0; p < 3; p++) {
        const __nv_bfloat16* Ab = (p == 2) ? Al : Ah;
        const __nv_bfloat16* Bb = (p == 1) ? Bl : Bh;
#pragma unroll
        for (int kk = 0; kk < 8; kk++) {
            const int k0 = kk * 16;
            uint32_t a[2][4], b[4][2];
#pragma unroll
            for (int mt = 0; mt < 2; mt++) {
                const __nv_bfloat16* base = Ab + (mrow + mt * 16 + fr) * LDA + k0 + fc;
                a[mt][0] = *(const uint32_t*)(base);
                a[mt][1] = *(const uint32_t*)(base + 8 * LDA);
                a[mt][2] = *(const uint32_t*)(base + 8);
                a[mt][3] = *(const uint32_t*)(base + 8 * LDA + 8);
            }
#pragma unroll
            for (int nt = 0; nt < 4; nt++) {
                const __nv_bfloat16* base = Bb + (ncol + nt * 8 + fr) * LDA + k0 + fc;
                b[nt][0] = *(const uint32_t*)(base);
                b[nt][1] = *(const uint32_t*)(base + 8);
            }
#pragma unroll
            for (int mt = 0; mt < 2; mt++)
#pragma unroll
                for (int nt = 0; nt < 4; nt++)
                    mma16816(acc[mt][nt], a[mt], b[nt]);
        }
    }

    // ---- epilogue: C fragment (m16n8): c0=(r,c) c1=(r,c+1) c2=(r+8,c) c3=(r+8,c+1) ----
#pragma unroll
    for (int mt = 0; mt < 2; mt++) {
#pragma unroll
        for (int nt = 0; nt < 4; nt++) {
            int m = m0 + mrow + mt * 16 + fr;
            int n = n0 + ncol + nt * 8 + fc;
#pragma unroll
            for (int half = 0; half < 2; half++) {
                int mm = m + half * 8;
                if (mm < NN) {
                    if (n < Nc)     g_h[(size_t)mm * Nc + n]     = acc[mt][nt][half * 2];
                    if (n + 1 < Nc) g_h[(size_t)mm * Nc + n + 1] = acc[mt][nt][half * 2 + 1];
                }
            }
        }
    }
}

// ---------------- aggregation: warp-per-node CSR gather ----------------
__global__ __launch_bounds__(256) void k_agg128(const float* __restrict__ b) {
    int w    = (blockIdx.x * blockDim.x + threadIdx.x) >> 5;
    int lane = threadIdx.x & 31;
    if (w >= NN) return;

    const float4* hv = (const float4*)g_h;
    int   s = g_start[w];
    int   e = g_start[w + 1];
    float d = g_dis[w];
    float dd = d * d;

    float4 acc = hv[(size_t)w * 32 + lane];
    acc.x = dd * acc.x + b[lane * 4 + 0];
    acc.y = dd * acc.y + b[lane * 4 + 1];
    acc.z = dd * acc.z + b[lane * 4 + 2];
    acc.w = dd * acc.w + b[lane * 4 + 3];

    for (int j = s; j < e; j++) {
        unsigned c = (unsigned)g_col[j];
        if (c >= NN) c = 0;
        float wn = g_norm[j];
        float4 v = hv[(size_t)c * 32 + lane];
        acc.x = fmaf(wn, v.x, acc.x);
        acc.y = fmaf(wn, v.y, acc.y);
        acc.z = fmaf(wn, v.z, acc.z);
        acc.w = fmaf(wn, v.w, acc.w);
    }
    ((float4*)g_agg)[(size_t)w * 32 + lane] = acc;
}

__global__ __launch_bounds__(256) void k_agg47(const float* __restrict__ b,
                                               float* __restrict__ out) {
    int w    = (blockIdx.x * blockDim.x + threadIdx.x) >> 5;
    int lane = threadIdx.x & 31;
    if (w >= NN) return;

    int   s = g_start[w];
    int   e = g_start[w + 1];
    float d = g_dis[w];
    float dd = d * d;
    bool  hi = (lane < 15);

    float acc0 = dd * g_h[(size_t)w * 47 + lane] + b[lane];
    float acc1 = hi ? (dd * g_h[(size_t)w * 47 + 32 + lane] + b[32 + lane]) : 0.0f;

    for (int j = s; j < e; j++) {
        unsigned c = (unsigned)g_col[j];
        if (c >= NN) c = 0;
        float wn = g_norm[j];
        acc0 = fmaf(wn, g_h[(size_t)c * 47 + lane], acc0);
        if (hi) acc1 = fmaf(wn, g_h[(size_t)c * 47 + 32 + lane], acc1);
    }
    out[(size_t)w * 47 + lane] = acc0;
    if (hi) out[(size_t)w * 47 + 32 + lane] = acc1;
}

// ---------------- launch ----------------
extern "C" void kernel_launch(void* const* d_in, const int* in_sizes, int n_in,
                              void* d_out, int out_size) {
    // ---- size-driven input identification ----
    const void*  ei = 0;
    const float *x = 0, *W1 = 0, *b1 = 0, *W2 = 0, *b2 = 0, *W3 = 0, *b3 = 0;
    int idx_ei = -1;
    int big[4], nbig = 0;
    int w16[4], nw16 = 0;
    int c128[4], nc128 = 0;
    for (int i = 0; i < n_in; i++) {
        int s = in_sizes[i];
        if (s == 3200000) { idx_ei = i; }
        else if (s == 12800000 && nbig < 4) big[nbig++] = i;
        else if (s == 16384  && nw16 < 4) w16[nw16++] = i;
        else if (s == 128    && nc128 < 4) c128[nc128++] = i;
        else if (s == 6016) W3 = (const float*)d_in[i];
        else if (s == 47)   b3 = (const float*)d_in[i];
    }
    ei = d_in[idx_ei];
    W1 = (const float*)d_in[w16[0]];  W2 = (const float*)d_in[w16[1]];
    b1 = (const float*)d_in[c128[0]]; b2 = (const float*)d_in[c128[1]];
    if (nbig == 2) x = (const float*)((big[0] < idx_ei) ? d_in[big[0]] : d_in[big[1]]);
    else           x = (const float*)d_in[big[0]];

    float* out = (float*)d_out;

    // dynamic smem: (2*128 + 2*64) * LDA * 2 bytes = 104448
    constexpr int SMEM_GEMM = (2 * 128 + 2 * 64) * LDA * 2;
    static bool attr_done = false;
    if (!attr_done) {
        cudaFuncSetAttribute(k_hmma<false, false>,
                             cudaFuncAttributeMaxDynamicSharedMemorySize, SMEM_GEMM);
        cudaFuncSetAttribute(k_hmma<true, true>,
                             cudaFuncAttributeMaxDynamicSharedMemorySize, SMEM_GEMM);
        attr_done = true;
    }

    // graph precompute
    k_dtype<<<1, 256>>>((const unsigned long long*)ei);
    k_zero <<<NB_SCAN, 256>>>();
    k_count<<<(EE + 255) / 256, 256>>>(ei);
    k_dis  <<<NB_SCAN, 256>>>();
    k_scan1<<<NB_SCAN, 256>>>();
    k_scan2<<<1, 512>>>();
    k_scan3<<<NB_SCAN, 256>>>();
    k_place<<<(EE + 255) / 256, 256>>>(ei);

    const dim3 gemm128((NN + 127) / 128, 2);   // Nc=128 -> 2 n-tiles
    const dim3 gemm47((NN + 127) / 128, 1);    // Nc=47  -> 1 n-tile
    const int  nb_agg = (NN * 32 + 255) / 256; // warp per node

    // layer 1
    k_hmma<false, false><<<gemm128, 256, SMEM_GEMM>>>(x, W1, 128);
    k_agg128<<<nb_agg, 256>>>(b1);
    // layer 2 (relu fused into A staging)
    k_hmma<true, true><<<gemm128, 256, SMEM_GEMM>>>(nullptr, W2, 128);
    k_agg128<<<nb_agg, 256>>>(b2);
    // layer 3 (47 outputs)
    k_hmma<true, true><<<gemm47, 256, SMEM_GEMM>>>(nullptr, W3, 47);
    k_agg47<<<nb_agg, 256>>>(b3, out);
}